// round 1
// baseline (speedup 1.0000x reference)
#include <cuda_runtime.h>

// Problem constants (fixed by setup_inputs)
constexpr int Bc  = 4;
constexpr int Nn  = 2048;
constexpr int Dd  = 256;   // in_dim == out_dim == H*hd
constexpr int Hh  = 4;
constexpr int HDd = 64;

constexpr int TI = 32;   // attention rows per block (main kernel)
constexpr int TJ = 64;   // j (key) tile

// Scratch (device globals — no runtime allocation allowed)
__device__ float g_Wh  [Bc * Nn * Dd];     // (B, N, 256) = Wh, h-major layout
__device__ float g_esrc[Bc * Hh * Nn];
__device__ float g_edst[Bc * Hh * Nn];
__device__ float g_mx  [Bc * Hh * Nn];
__device__ float g_inv [Bc * Hh * Nn];

// Packed fp32x2 FMA: d = {a,a} * w + c   (ptxas will not auto-fuse; PTX only)
__device__ __forceinline__ float2 ffma2f(float a, float2 w, float2 c) {
    union U { float2 f2; unsigned long long u; };
    U ua, uw, uc, ud;
    ua.f2 = make_float2(a, a);
    uw.f2 = w;
    uc.f2 = c;
    asm("fma.rn.f32x2 %0, %1, %2, %3;" : "=l"(ud.u) : "l"(ua.u), "l"(uw.u), "l"(uc.u));
    return ud.f2;
}

// ---------------------------------------------------------------------------
// Kernel 1: Wh = h @ W   (M=8192, K=256, N=256) fp32 tiled GEMM
// ---------------------------------------------------------------------------
__global__ __launch_bounds__(256)
void gemm_h_w(const float* __restrict__ A, const float* __restrict__ Bw) {
    __shared__ float As[16][64];
    __shared__ float Bs[16][64];
    const int tid = threadIdx.x;
    const int m0 = blockIdx.x * 64;
    const int n0 = blockIdx.y * 64;
    const int tm = tid >> 4, tn = tid & 15;
    const int lm = tid >> 2, lk = (tid & 3) * 4;
    const int lbk = tid >> 4, lbn = (tid & 15) * 4;

    float acc[4][4];
#pragma unroll
    for (int r = 0; r < 4; r++)
#pragma unroll
        for (int c = 0; c < 4; c++) acc[r][c] = 0.f;

    for (int k0 = 0; k0 < 256; k0 += 16) {
        float4 av = *(const float4*)(A + (size_t)(m0 + lm) * 256 + k0 + lk);
        As[lk + 0][lm] = av.x; As[lk + 1][lm] = av.y;
        As[lk + 2][lm] = av.z; As[lk + 3][lm] = av.w;
        *(float4*)&Bs[lbk][lbn] =
            *(const float4*)(Bw + (size_t)(k0 + lbk) * 256 + n0 + lbn);
        __syncthreads();
#pragma unroll
        for (int k = 0; k < 16; k++) {
            float4 a4 = *(const float4*)&As[k][tm * 4];
            float4 b4 = *(const float4*)&Bs[k][tn * 4];
            float ar[4] = {a4.x, a4.y, a4.z, a4.w};
            float br[4] = {b4.x, b4.y, b4.z, b4.w};
#pragma unroll
            for (int r = 0; r < 4; r++)
#pragma unroll
                for (int c = 0; c < 4; c++) acc[r][c] += ar[r] * br[c];
        }
        __syncthreads();
    }
#pragma unroll
    for (int r = 0; r < 4; r++)
        *(float4*)(g_Wh + (size_t)(m0 + tm * 4 + r) * 256 + n0 + tn * 4) =
            make_float4(acc[r][0], acc[r][1], acc[r][2], acc[r][3]);
}

// ---------------------------------------------------------------------------
// Kernel 2: e_src[b,h,n] = Wh[b,n,h*64:] . a_src[h],  same for e_dst
// One warp per (b,h,n) row.
// ---------------------------------------------------------------------------
__global__ __launch_bounds__(256)
void gat_attn_proj(const float* __restrict__ a_src, const float* __restrict__ a_dst) {
    int r = blockIdx.x * 8 + (threadIdx.x >> 5);
    int lane = threadIdx.x & 31;
    int b = r >> 13, h = (r >> 11) & 3, n = r & (Nn - 1);
    const float* wp = g_Wh + ((size_t)(b * Nn + n)) * Dd + h * HDd;
    float2 w  = *(const float2*)(wp + 2 * lane);
    float2 as = *(const float2*)(a_src + h * HDd + 2 * lane);
    float2 ad = *(const float2*)(a_dst + h * HDd + 2 * lane);
    float ss = w.x * as.x + w.y * as.y;
    float sd = w.x * ad.x + w.y * ad.y;
#pragma unroll
    for (int o = 16; o; o >>= 1) {
        ss += __shfl_xor_sync(0xffffffffu, ss, o);
        sd += __shfl_xor_sync(0xffffffffu, sd, o);
    }
    if (lane == 0) { g_esrc[r] = ss; g_edst[r] = sd; }
}

// ---------------------------------------------------------------------------
// Kernel 3: per-row softmax stats (max, 1/sum) for all 4 heads.
// One block per (b, i); adj row read once, e kept in registers for pass 2.
// ---------------------------------------------------------------------------
__global__ __launch_bounds__(256)
void gat_stats(const int* __restrict__ adj) {
    const int b = blockIdx.x >> 11;
    const int i = blockIdx.x & (Nn - 1);
    const int tid  = threadIdx.x;
    const int lane = tid & 31;
    const int warp = tid >> 5;

    float es[4];
#pragma unroll
    for (int h = 0; h < 4; h++) es[h] = g_esrc[(b * Hh + h) * Nn + i];

    float ev[8][4];
    float m[4] = {-1e30f, -1e30f, -1e30f, -1e30f};
    const size_t arow = (size_t)(b * Nn + i) * Nn;
#pragma unroll
    for (int k = 0; k < 8; k++) {
        int j = tid + k * 256;
        int a = adj[arow + j];
#pragma unroll
        for (int h = 0; h < 4; h++) {
            float e = es[h] + g_edst[(b * Hh + h) * Nn + j];
            e = (e > 0.f) ? e : 0.2f * e;
            e = a ? e : -1e30f;
            ev[k][h] = e;
            m[h] = fmaxf(m[h], e);
        }
    }

    __shared__ float sred[4][8];
    __shared__ float sfin[4];
#pragma unroll
    for (int h = 0; h < 4; h++)
#pragma unroll
        for (int o = 16; o; o >>= 1)
            m[h] = fmaxf(m[h], __shfl_xor_sync(0xffffffffu, m[h], o));
    if (lane == 0)
#pragma unroll
        for (int h = 0; h < 4; h++) sred[h][warp] = m[h];
    __syncthreads();
    if (tid == 0) {
#pragma unroll
        for (int h = 0; h < 4; h++) {
            float mm = sred[h][0];
#pragma unroll
            for (int w2 = 1; w2 < 8; w2++) mm = fmaxf(mm, sred[h][w2]);
            sfin[h] = mm;
        }
    }
    __syncthreads();
    float M[4];
#pragma unroll
    for (int h = 0; h < 4; h++) M[h] = sfin[h];

    float s[4] = {0.f, 0.f, 0.f, 0.f};
#pragma unroll
    for (int k = 0; k < 8; k++)
#pragma unroll
        for (int h = 0; h < 4; h++) s[h] += __expf(ev[k][h] - M[h]);
#pragma unroll
    for (int h = 0; h < 4; h++)
#pragma unroll
        for (int o = 16; o; o >>= 1)
            s[h] += __shfl_xor_sync(0xffffffffu, s[h], o);
    __syncthreads();
    if (lane == 0)
#pragma unroll
        for (int h = 0; h < 4; h++) sred[h][warp] = s[h];
    __syncthreads();
    if (tid < 4) {
        int h = tid;
        float S = 0.f;
#pragma unroll
        for (int w2 = 0; w2 < 8; w2++) S += sred[h][w2];
        int g = (b * Hh + h) * Nn + i;
        g_mx[g] = M[h];
        g_inv[g] = (M[h] > -1e29f) ? (1.f / S) : 0.f;  // empty row -> alpha = 0
    }
}

// ---------------------------------------------------------------------------
// Kernel 4 (main, fused): alpha materialization + h_out = alpha @ Wh.
// Block = (b, 32-row tile). Wh j-tiles staged in shared; alpha computed once
// into shared (and streamed to gmem), consumed by an f32x2 micro-GEMM.
// 512 threads = 128 col-pairs x 2 i-halves x 2 j-parities.
// ---------------------------------------------------------------------------
constexpr int SMEM_MAIN = (TJ * Dd + Hh * TJ * (TI + 4) + 3 * TI * Hh) * 4;

__global__ __launch_bounds__(512, 1)
void gat_main(const int* __restrict__ adj,
              float* __restrict__ h_out,
              float* __restrict__ alpha_out,
              int write_alpha) {
    extern __shared__ float smem[];
    float* Whs = smem;                     // [TJ][256]           16384 floats
    float* ash = smem + TJ * Dd;           // [4][64][36]          9216 floats
    float* es  = ash + Hh * TJ * (TI + 4); // [TI][4]
    float* mx  = es + TI * Hh;
    float* iv  = mx + TI * Hh;

    const int tid = threadIdx.x;
    const int b   = blockIdx.x / (Nn / TI);
    const int i0  = (blockIdx.x % (Nn / TI)) * TI;

    if (tid < TI * Hh) {
        int i = tid >> 2, h = tid & 3;
        int g = (b * Hh + h) * Nn + i0 + i;
        es[tid] = g_esrc[g];
        mx[tid] = g_mx[g];
        iv[tid] = g_inv[g];
    }

    // alpha-phase mapping
    const int a_h  = (tid >> 6) & 3;
    const int a_j  = tid & 63;
    const int a_i0 = (tid >> 8) * 16;
    // gemm mapping
    const int cp  = tid & 127;      // output columns 2cp, 2cp+1
    const int ih2 = (tid >> 7) & 1; // i half (16 rows each)
    const int jh  = tid >> 8;       // j parity
    const int gh  = cp >> 5;        // head of this column pair

    float2 acc[16];
#pragma unroll
    for (int i = 0; i < 16; i++) acc[i] = make_float2(0.f, 0.f);

    const float* ap_base = ash + (gh * 64) * (TI + 4) + ih2 * 16;

    for (int jt = 0; jt < Nn / TJ; jt++) {
        const int j0 = jt * TJ;
        __syncthreads();
        // stage Wh[b, j0:j0+64, :] (contiguous 64KB) into shared
        {
            const float4* src = (const float4*)(g_Wh + ((size_t)b * Nn + j0) * Dd);
            float4* dst = (float4*)Whs;
#pragma unroll
            for (int r = 0; r < 8; r++) dst[tid + r * 512] = src[tid + r * 512];
        }
        // compute alpha for (a_h, j0+a_j) over 16 rows; stash + stream out
        {
            const float ed = g_edst[(b * Hh + a_h) * Nn + j0 + a_j];
            const size_t adjbase = ((size_t)(b * Nn + i0 + a_i0)) * Nn + j0 + a_j;
            float* ao = alpha_out +
                ((size_t)(b * Hh + a_h) * Nn + i0 + a_i0) * Nn + j0 + a_j;
#pragma unroll
            for (int ii = 0; ii < 16; ii++) {
                int i = a_i0 + ii;
                int mk = adj[adjbase + (size_t)ii * Nn];
                float e = es[i * 4 + a_h] + ed;
                e = (e > 0.f) ? e : 0.2f * e;
                float al = mk ? __expf(e - mx[i * 4 + a_h]) * iv[i * 4 + a_h] : 0.f;
                ash[(a_h * 64 + a_j) * (TI + 4) + i] = al;
                if (write_alpha) ao[(size_t)ii * Nn] = al;
            }
        }
        __syncthreads();
        // micro-GEMM: acc[i] += alpha[i] * Wh[j][2cp..2cp+1], packed f32x2
#pragma unroll 4
        for (int j = jh; j < TJ; j += 2) {
            float2 w = *(const float2*)(Whs + j * Dd + 2 * cp);
            const float* ap = ap_base + j * (TI + 4);
            float4 a0 = *(const float4*)(ap);
            float4 a1 = *(const float4*)(ap + 4);
            float4 a2 = *(const float4*)(ap + 8);
            float4 a3 = *(const float4*)(ap + 12);
            acc[0]  = ffma2f(a0.x, w, acc[0]);
            acc[1]  = ffma2f(a0.y, w, acc[1]);
            acc[2]  = ffma2f(a0.z, w, acc[2]);
            acc[3]  = ffma2f(a0.w, w, acc[3]);
            acc[4]  = ffma2f(a1.x, w, acc[4]);
            acc[5]  = ffma2f(a1.y, w, acc[5]);
            acc[6]  = ffma2f(a1.z, w, acc[6]);
            acc[7]  = ffma2f(a1.w, w, acc[7]);
            acc[8]  = ffma2f(a2.x, w, acc[8]);
            acc[9]  = ffma2f(a2.y, w, acc[9]);
            acc[10] = ffma2f(a2.z, w, acc[10]);
            acc[11] = ffma2f(a2.w, w, acc[11]);
            acc[12] = ffma2f(a3.x, w, acc[12]);
            acc[13] = ffma2f(a3.y, w, acc[13]);
            acc[14] = ffma2f(a3.z, w, acc[14]);
            acc[15] = ffma2f(a3.w, w, acc[15]);
        }
    }

    // reduce the two j-parity partials, write h_out
    __syncthreads();
    float2* red = (float2*)smem;        // reuse Whs region (34KB < 64KB)
    const int rid = ih2 * 128 + cp;
    if (jh == 1) {
#pragma unroll
        for (int i = 0; i < 16; i++) red[rid * 17 + i] = acc[i];
    }
    __syncthreads();
    if (jh == 0) {
        float* op = h_out + ((size_t)(b * Nn) + i0 + ih2 * 16) * Dd + 2 * cp;
#pragma unroll
        for (int i = 0; i < 16; i++) {
            float2 r = red[rid * 17 + i];
            acc[i].x += r.x;
            acc[i].y += r.y;
            *(float2*)(op + (size_t)i * Dd) = acc[i];
        }
    }
}

// ---------------------------------------------------------------------------
extern "C" void kernel_launch(void* const* d_in, const int* in_sizes, int n_in,
                              void* d_out, int out_size) {
    const float* h     = (const float*)d_in[0];
    const int*   adj   = (const int*)d_in[1];
    const float* W     = (const float*)d_in[2];
    const float* a_src = (const float*)d_in[3];
    const float* a_dst = (const float*)d_in[4];
    float* out = (float*)d_out;

    const long long houtN  = (long long)Bc * Nn * Dd;          //  2,097,152
    const long long alphaN = (long long)Bc * Hh * Nn * Nn;     // 67,108,864
    int write_alpha = ((long long)out_size >= houtN + alphaN) ? 1 : 0;
    float* alpha_out = out + houtN;

    cudaFuncSetAttribute(gat_main, cudaFuncAttributeMaxDynamicSharedMemorySize,
                         SMEM_MAIN);

    gemm_h_w<<<dim3(128, 4), 256>>>(h, W);
    gat_attn_proj<<<(Bc * Hh * Nn) / 8, 256>>>(a_src, a_dst);
    gat_stats<<<Bc * Nn, 256>>>(adj);
    gat_main<<<Bc * (Nn / TI), 512, SMEM_MAIN>>>(adj, out, alpha_out, write_alpha);
}

// round 2
// speedup vs baseline: 1.0767x; 1.0767x over previous
#include <cuda_runtime.h>

// Problem constants (fixed by setup_inputs)
constexpr int Bc  = 4;
constexpr int Nn  = 2048;
constexpr int Dd  = 256;   // in_dim == out_dim == H*hd
constexpr int Hh  = 4;
constexpr int HDd = 64;

constexpr int TI = 32;   // attention rows per block (main kernel)
constexpr int TJ = 64;   // j (key) tile
constexpr int AS = TI + 4; // alpha smem stride (36: 16B-aligned, staggers banks)

// Scratch (device globals — no runtime allocation allowed)
__device__ float g_Wh  [Bc * Nn * Dd];
__device__ float g_esrc[Bc * Hh * Nn];
__device__ float g_edst[Bc * Hh * Nn];
__device__ float g_mx  [Bc * Hh * Nn];
__device__ float g_inv [Bc * Hh * Nn];

// Packed fp32x2 FMA: d = {a,a} * w + c
__device__ __forceinline__ float2 ffma2f(float a, float2 w, float2 c) {
    union U { float2 f2; unsigned long long u; };
    U ua, uw, uc, ud;
    ua.f2 = make_float2(a, a);
    uw.f2 = w;
    uc.f2 = c;
    asm("fma.rn.f32x2 %0, %1, %2, %3;" : "=l"(ud.u) : "l"(ua.u), "l"(uw.u), "l"(uc.u));
    return ud.f2;
}

__device__ __forceinline__ void cpasync16(void* smem, const void* gmem) {
    unsigned s = (unsigned)__cvta_generic_to_shared(smem);
    asm volatile("cp.async.cg.shared.global [%0], [%1], 16;" :: "r"(s), "l"(gmem));
}
#define CP_COMMIT() asm volatile("cp.async.commit_group;")
#define CP_WAIT0()  asm volatile("cp.async.wait_group 0;")

// ---------------------------------------------------------------------------
// Kernel 1: Wh = h @ W   (M=8192, K=256, N=256) fp32 tiled GEMM
// ---------------------------------------------------------------------------
__global__ __launch_bounds__(256)
void gemm_h_w(const float* __restrict__ A, const float* __restrict__ Bw) {
    __shared__ float As[16][64];
    __shared__ float Bs[16][64];
    const int tid = threadIdx.x;
    const int m0 = blockIdx.x * 64;
    const int n0 = blockIdx.y * 64;
    const int tm = tid >> 4, tn = tid & 15;
    const int lm = tid >> 2, lk = (tid & 3) * 4;
    const int lbk = tid >> 4, lbn = (tid & 15) * 4;

    float acc[4][4];
#pragma unroll
    for (int r = 0; r < 4; r++)
#pragma unroll
        for (int c = 0; c < 4; c++) acc[r][c] = 0.f;

    for (int k0 = 0; k0 < 256; k0 += 16) {
        float4 av = *(const float4*)(A + (size_t)(m0 + lm) * 256 + k0 + lk);
        As[lk + 0][lm] = av.x; As[lk + 1][lm] = av.y;
        As[lk + 2][lm] = av.z; As[lk + 3][lm] = av.w;
        *(float4*)&Bs[lbk][lbn] =
            *(const float4*)(Bw + (size_t)(k0 + lbk) * 256 + n0 + lbn);
        __syncthreads();
#pragma unroll
        for (int k = 0; k < 16; k++) {
            float4 a4 = *(const float4*)&As[k][tm * 4];
            float4 b4 = *(const float4*)&Bs[k][tn * 4];
            float ar[4] = {a4.x, a4.y, a4.z, a4.w};
            float br[4] = {b4.x, b4.y, b4.z, b4.w};
#pragma unroll
            for (int r = 0; r < 4; r++)
#pragma unroll
                for (int c = 0; c < 4; c++) acc[r][c] += ar[r] * br[c];
        }
        __syncthreads();
    }
#pragma unroll
    for (int r = 0; r < 4; r++)
        *(float4*)(g_Wh + (size_t)(m0 + tm * 4 + r) * 256 + n0 + tn * 4) =
            make_float4(acc[r][0], acc[r][1], acc[r][2], acc[r][3]);
}

// ---------------------------------------------------------------------------
// Kernel 2: e_src / e_dst projections. One warp per (b,h,n).
// ---------------------------------------------------------------------------
__global__ __launch_bounds__(256)
void gat_attn_proj(const float* __restrict__ a_src, const float* __restrict__ a_dst) {
    int r = blockIdx.x * 8 + (threadIdx.x >> 5);
    int lane = threadIdx.x & 31;
    int b = r >> 13, h = (r >> 11) & 3, n = r & (Nn - 1);
    const float* wp = g_Wh + ((size_t)(b * Nn + n)) * Dd + h * HDd;
    float2 w  = *(const float2*)(wp + 2 * lane);
    float2 as = *(const float2*)(a_src + h * HDd + 2 * lane);
    float2 ad = *(const float2*)(a_dst + h * HDd + 2 * lane);
    float ss = w.x * as.x + w.y * as.y;
    float sd = w.x * ad.x + w.y * ad.y;
#pragma unroll
    for (int o = 16; o; o >>= 1) {
        ss += __shfl_xor_sync(0xffffffffu, ss, o);
        sd += __shfl_xor_sync(0xffffffffu, sd, o);
    }
    if (lane == 0) { g_esrc[r] = ss; g_edst[r] = sd; }
}

// ---------------------------------------------------------------------------
// Kernel 3: per-row softmax stats (max, 1/sum), all 4 heads per block.
// ---------------------------------------------------------------------------
__global__ __launch_bounds__(256)
void gat_stats(const int* __restrict__ adj) {
    const int b = blockIdx.x >> 11;
    const int i = blockIdx.x & (Nn - 1);
    const int tid  = threadIdx.x;
    const int lane = tid & 31;
    const int warp = tid >> 5;

    float es[4];
#pragma unroll
    for (int h = 0; h < 4; h++) es[h] = g_esrc[(b * Hh + h) * Nn + i];

    float ev[8][4];
    float m[4] = {-1e30f, -1e30f, -1e30f, -1e30f};
    const size_t arow = (size_t)(b * Nn + i) * Nn;
#pragma unroll
    for (int k = 0; k < 8; k++) {
        int j = tid + k * 256;
        int a = adj[arow + j];
#pragma unroll
        for (int h = 0; h < 4; h++) {
            float e = es[h] + g_edst[(b * Hh + h) * Nn + j];
            e = (e > 0.f) ? e : 0.2f * e;
            e = a ? e : -1e30f;
            ev[k][h] = e;
            m[h] = fmaxf(m[h], e);
        }
    }

    __shared__ float sred[4][8];
    __shared__ float sfin[4];
#pragma unroll
    for (int h = 0; h < 4; h++)
#pragma unroll
        for (int o = 16; o; o >>= 1)
            m[h] = fmaxf(m[h], __shfl_xor_sync(0xffffffffu, m[h], o));
    if (lane == 0)
#pragma unroll
        for (int h = 0; h < 4; h++) sred[h][warp] = m[h];
    __syncthreads();
    if (tid == 0) {
#pragma unroll
        for (int h = 0; h < 4; h++) {
            float mm = sred[h][0];
#pragma unroll
            for (int w2 = 1; w2 < 8; w2++) mm = fmaxf(mm, sred[h][w2]);
            sfin[h] = mm;
        }
    }
    __syncthreads();
    float M[4];
#pragma unroll
    for (int h = 0; h < 4; h++) M[h] = sfin[h];

    float s[4] = {0.f, 0.f, 0.f, 0.f};
#pragma unroll
    for (int k = 0; k < 8; k++)
#pragma unroll
        for (int h = 0; h < 4; h++) s[h] += __expf(ev[k][h] - M[h]);
#pragma unroll
    for (int h = 0; h < 4; h++)
#pragma unroll
        for (int o = 16; o; o >>= 1)
            s[h] += __shfl_xor_sync(0xffffffffu, s[h], o);
    __syncthreads();
    if (lane == 0)
#pragma unroll
        for (int h = 0; h < 4; h++) sred[h][warp] = s[h];
    __syncthreads();
    if (tid < 4) {
        int h = tid;
        float S = 0.f;
#pragma unroll
        for (int w2 = 0; w2 < 8; w2++) S += sred[h][w2];
        int g = (b * Hh + h) * Nn + i;
        g_mx[g] = M[h];
        g_inv[g] = (M[h] > -1e29f) ? (1.f / S) : 0.f;
    }
}

// ---------------------------------------------------------------------------
// Kernel 4 (main): software-pipelined alpha + h_out = alpha @ Wh.
// Double-buffered Whs (cp.async) and alpha tiles; 1 barrier per j-tile.
// 512 threads:
//   gemm map : cq = tid&63 (cols 4cq..4cq+3), ig = (tid>>6)&3 (rows ig*8..+7),
//              jh = tid>>8 (j parity)
//   alpha map: a_h = (tid>>6)&3, a_j = tid&63, a_half = (tid>>8)*16
// ---------------------------------------------------------------------------
constexpr int WHS_F  = TJ * Dd;            // 16384 floats per buffer
constexpr int ASH_F  = Hh * TJ * AS;       //  9216 floats per buffer
constexpr int SMEM_MAIN = (2 * WHS_F + 2 * ASH_F + 3 * TI * Hh) * 4;

__global__ __launch_bounds__(512, 1)
void gat_main(const int* __restrict__ adj,
              float* __restrict__ h_out,
              float* __restrict__ alpha_out,
              int write_alpha) {
    extern __shared__ float smem[];
    float* whs[2] = { smem, smem + WHS_F };
    float* ash[2] = { smem + 2 * WHS_F, smem + 2 * WHS_F + ASH_F };
    float* es = smem + 2 * WHS_F + 2 * ASH_F;   // [TI*Hh], index i*4+h
    float* mx = es + TI * Hh;
    float* iv = mx + TI * Hh;

    const int tid = threadIdx.x;
    const int b   = blockIdx.x / (Nn / TI);
    const int i0  = (blockIdx.x % (Nn / TI)) * TI;

    if (tid < TI * Hh) {
        int g = (b * Hh + (tid & 3)) * Nn + i0 + (tid >> 2);
        es[tid] = g_esrc[g];
        mx[tid] = g_mx[g];
        iv[tid] = g_inv[g];
    }

    // gemm mapping
    const int cq = tid & 63;
    const int ig = (tid >> 6) & 3;
    const int jh = tid >> 8;
    const int gh = cq >> 4;
    // alpha mapping
    const int a_h    = (tid >> 6) & 3;
    const int a_j    = tid & 63;
    const int a_half = (tid >> 8) * 16;

    const float4* wh_src = (const float4*)(g_Wh + ((size_t)b * Nn) * Dd);
    const int*   adj_b   = adj + ((size_t)(b * Nn + i0 + a_half)) * Nn + a_j;
    const float* edst_b  = g_edst + (b * Hh + a_h) * Nn + a_j;
    float*       alp_b   = alpha_out +
        ((size_t)(b * Hh + a_h) * Nn + i0 + a_half) * Nn + a_j;

    float2 acc[8][2];
#pragma unroll
    for (int r = 0; r < 8; r++) { acc[r][0] = make_float2(0.f, 0.f);
                                  acc[r][1] = make_float2(0.f, 0.f); }

    int   adjreg[16];
    float edreg;

    // ---- prologue: stage tile 0, compute alpha(0) ----
    {
        float4* dst = (float4*)whs[0];
        const float4* src = wh_src;            // j0 = 0
#pragma unroll
        for (int r = 0; r < 8; r++) cpasync16(dst + tid + r * 512, src + tid + r * 512);
        CP_COMMIT();

#pragma unroll
        for (int ii = 0; ii < 16; ii++) adjreg[ii] = adj_b[(size_t)ii * Nn];
        edreg = edst_b[0];

        __syncthreads();   // es/mx/iv visible
        float* dsta = ash[0] + (a_h * 64 + a_j) * AS;
#pragma unroll
        for (int ii = 0; ii < 16; ii++) {
            int i = a_half + ii;
            float e = es[i * 4 + a_h] + edreg;
            e = (e > 0.f) ? e : 0.2f * e;
            float al = adjreg[ii] ? __expf(e - mx[i * 4 + a_h]) * iv[i * 4 + a_h] : 0.f;
            dsta[i] = al;
            if (write_alpha) alp_b[(size_t)ii * Nn] = al;
        }
        CP_WAIT0();
        __syncthreads();
    }

    // ---- main pipelined loop over j tiles ----
    for (int t = 0; t < Nn / TJ; t++) {
        const int buf = t & 1;
        const int tn  = t + 1;
        if (tn < Nn / TJ) {
            // stage Wh(t+1) async + prefetch adj/edst(t+1) into regs
            float4* dst = (float4*)whs[buf ^ 1];
            const float4* src = wh_src + (size_t)tn * (TJ * Dd / 4);
#pragma unroll
            for (int r = 0; r < 8; r++)
                cpasync16(dst + tid + r * 512, src + tid + r * 512);
            CP_COMMIT();
#pragma unroll
            for (int ii = 0; ii < 16; ii++)
                adjreg[ii] = adj_b[(size_t)ii * Nn + tn * TJ];
            edreg = edst_b[tn * TJ];
        }

        // gemm on buffer `buf`
        {
            const float* wb = whs[buf] + 4 * cq;
            const float* ab = ash[buf] + (gh * 64) * AS + ig * 8;
#pragma unroll 4
            for (int j = jh; j < TJ; j += 2) {
                float4 w = *(const float4*)(wb + j * Dd);
                float2 w01 = make_float2(w.x, w.y);
                float2 w23 = make_float2(w.z, w.w);
                const float* ap = ab + j * AS;
                float4 a0 = *(const float4*)(ap);
                float4 a1 = *(const float4*)(ap + 4);
                acc[0][0] = ffma2f(a0.x, w01, acc[0][0]);
                acc[0][1] = ffma2f(a0.x, w23, acc[0][1]);
                acc[1][0] = ffma2f(a0.y, w01, acc[1][0]);
                acc[1][1] = ffma2f(a0.y, w23, acc[1][1]);
                acc[2][0] = ffma2f(a0.z, w01, acc[2][0]);
                acc[2][1] = ffma2f(a0.z, w23, acc[2][1]);
                acc[3][0] = ffma2f(a0.w, w01, acc[3][0]);
                acc[3][1] = ffma2f(a0.w, w23, acc[3][1]);
                acc[4][0] = ffma2f(a1.x, w01, acc[4][0]);
                acc[4][1] = ffma2f(a1.x, w23, acc[4][1]);
                acc[5][0] = ffma2f(a1.y, w01, acc[5][0]);
                acc[5][1] = ffma2f(a1.y, w23, acc[5][1]);
                acc[6][0] = ffma2f(a1.z, w01, acc[6][0]);
                acc[6][1] = ffma2f(a1.z, w23, acc[6][1]);
                acc[7][0] = ffma2f(a1.w, w01, acc[7][0]);
                acc[7][1] = ffma2f(a1.w, w23, acc[7][1]);
            }
        }

        // alpha(t+1) into the other buffer (safe: gemm(t-1) on it finished
        // at the barrier ending iteration t-1)
        if (tn < Nn / TJ) {
            float* dsta = ash[buf ^ 1] + (a_h * 64 + a_j) * AS;
            float* ao   = alp_b + tn * TJ;
#pragma unroll
            for (int ii = 0; ii < 16; ii++) {
                int i = a_half + ii;
                float e = es[i * 4 + a_h] + edreg;
                e = (e > 0.f) ? e : 0.2f * e;
                float al = adjreg[ii] ? __expf(e - mx[i * 4 + a_h]) * iv[i * 4 + a_h] : 0.f;
                dsta[i] = al;
                if (write_alpha) ao[(size_t)ii * Nn] = al;
            }
        }
        CP_WAIT0();
        __syncthreads();
    }

    // ---- reduce the two j-parity partials, write h_out ----
    float4* red = (float4*)smem;   // reuse Whs region (32KB needed)
    const int rid = ig * 64 + cq;  // 0..255
    if (jh == 1) {
#pragma unroll
        for (int r = 0; r < 8; r++)
            red[rid * 8 + r] = make_float4(acc[r][0].x, acc[r][0].y,
                                           acc[r][1].x, acc[r][1].y);
    }
    __syncthreads();
    if (jh == 0) {
        float* op = h_out + ((size_t)(b * Nn) + i0 + ig * 8) * Dd + 4 * cq;
#pragma unroll
        for (int r = 0; r < 8; r++) {
            float4 p = red[rid * 8 + r];
            p.x += acc[r][0].x; p.y += acc[r][0].y;
            p.z += acc[r][1].x; p.w += acc[r][1].y;
            *(float4*)(op + (size_t)r * Dd) = p;
        }
    }
}

// ---------------------------------------------------------------------------
extern "C" void kernel_launch(void* const* d_in, const int* in_sizes, int n_in,
                              void* d_out, int out_size) {
    const float* h     = (const float*)d_in[0];
    const int*   adj   = (const int*)d_in[1];
    const float* W     = (const float*)d_in[2];
    const float* a_src = (const float*)d_in[3];
    const float* a_dst = (const float*)d_in[4];
    float* out = (float*)d_out;

    const long long houtN  = (long long)Bc * Nn * Dd;
    const long long alphaN = (long long)Bc * Hh * Nn * Nn;
    int write_alpha = ((long long)out_size >= houtN + alphaN) ? 1 : 0;
    float* alpha_out = out + houtN;

    cudaFuncSetAttribute(gat_main, cudaFuncAttributeMaxDynamicSharedMemorySize,
                         SMEM_MAIN);

    gemm_h_w<<<dim3(128, 4), 256>>>(h, W);
    gat_attn_proj<<<(Bc * Hh * Nn) / 8, 256>>>(a_src, a_dst);
    gat_stats<<<Bc * Nn, 256>>>(adj);
    gat_main<<<Bc * (Nn / TI), 512, SMEM_MAIN>>>(adj, out, alpha_out, write_alpha);
}